// round 1
// baseline (speedup 1.0000x reference)
#include <cuda_runtime.h>
#include <cstdint>

// Problem constants (fixed by the reference)
#define NN 100000
#define HIDC 128

// Scratch (device globals — no allocation allowed)
__device__ __align__(16) float g_h[NN * HIDC];
__device__ __align__(16) float g_t1[NN * HIDC];
__device__ __align__(16) float g_t2[NN * HIDC];
__device__ __align__(16) float g_u1[NN * HIDC];
__device__ __align__(16) float g_u2[NN * HIDC];
__device__ __align__(16) float g_acc[NN * HIDC];
__device__ int g_rp[NN + 1];

// ---------------------------------------------------------------------------
// row_ptr via binary search over the sorted row array
// ---------------------------------------------------------------------------
__global__ void rowptr_kernel(const int* __restrict__ row, int E, int n,
                              int* __restrict__ rp) {
    int i = blockIdx.x * blockDim.x + threadIdx.x;
    if (i > n) return;
    int lo = 0, hi = E;
    while (lo < hi) {
        int mid = (lo + hi) >> 1;
        if (row[mid] < i) lo = mid + 1; else hi = mid;
    }
    rp[i] = lo;
}

// ---------------------------------------------------------------------------
// Tiled fp32 SGEMM: C = scale*(A@B) [+bias] [relu]
// A: [M,K] row-major, B: [K,N] row-major, C: [M,N]
// ---------------------------------------------------------------------------
template <int BM, int BN, int BK, int TM, int TN, bool RELU, bool BIAS>
__global__ void sgemm_kernel(const float* __restrict__ A,
                             const float* __restrict__ B,
                             const float* __restrict__ bias,
                             float* __restrict__ C,
                             int M, int N, int K, float scale) {
    constexpr int NTHR = (BM / TM) * (BN / TN);
    __shared__ float As[BK][BM];
    __shared__ float Bs[BK][BN];

    const int tid = threadIdx.x;
    const int bm = blockIdx.x * BM;
    const int bn = blockIdx.y * BN;
    const int tcol = tid % (BN / TN);
    const int trow = tid / (BN / TN);

    float acc[TM][TN];
#pragma unroll
    for (int i = 0; i < TM; i++)
#pragma unroll
        for (int j = 0; j < TN; j++) acc[i][j] = 0.0f;

    for (int k0 = 0; k0 < K; k0 += BK) {
        // A tile [BM x BK] -> As[k][m] (transposed)
#pragma unroll
        for (int i = tid; i < BM * BK / 4; i += NTHR) {
            int r = i / (BK / 4);
            int kq = i % (BK / 4);
            int grow = bm + r;
            float4 v = make_float4(0.f, 0.f, 0.f, 0.f);
            if (grow < M)
                v = *(const float4*)&A[(size_t)grow * K + k0 + 4 * kq];
            As[4 * kq + 0][r] = v.x;
            As[4 * kq + 1][r] = v.y;
            As[4 * kq + 2][r] = v.z;
            As[4 * kq + 3][r] = v.w;
        }
        // B tile [BK x BN]
#pragma unroll
        for (int i = tid; i < BK * BN / 4; i += NTHR) {
            int r = i / (BN / 4);
            int cq = i % (BN / 4);
            float4 v = *(const float4*)&B[(size_t)(k0 + r) * N + bn + 4 * cq];
            *(float4*)&Bs[r][4 * cq] = v;
        }
        __syncthreads();

#pragma unroll
        for (int kk = 0; kk < BK; kk++) {
            float ra[TM], rb[TN];
#pragma unroll
            for (int i = 0; i < TM; i += 4)
                *(float4*)&ra[i] = *(float4*)&As[kk][trow * TM + i];
#pragma unroll
            for (int j = 0; j < TN; j += 4)
                *(float4*)&rb[j] = *(float4*)&Bs[kk][tcol * TN + j];
#pragma unroll
            for (int i = 0; i < TM; i++)
#pragma unroll
                for (int j = 0; j < TN; j++)
                    acc[i][j] = fmaf(ra[i], rb[j], acc[i][j]);
        }
        __syncthreads();
    }

    // epilogue
#pragma unroll
    for (int i = 0; i < TM; i++) {
        int grow = bm + trow * TM + i;
        if (grow >= M) continue;
#pragma unroll
        for (int j = 0; j < TN; j += 4) {
            int gcol = bn + tcol * TN + j;
            float4 v;
            v.x = acc[i][j + 0] * scale;
            v.y = acc[i][j + 1] * scale;
            v.z = acc[i][j + 2] * scale;
            v.w = acc[i][j + 3] * scale;
            if (BIAS) {
                v.x += bias[gcol + 0];
                v.y += bias[gcol + 1];
                v.z += bias[gcol + 2];
                v.w += bias[gcol + 3];
            }
            if (RELU) {
                v.x = fmaxf(v.x, 0.f);
                v.y = fmaxf(v.y, 0.f);
                v.z = fmaxf(v.z, 0.f);
                v.w = fmaxf(v.w, 0.f);
            }
            *(float4*)&C[(size_t)grow * N + gcol] = v;
        }
    }
}

// ---------------------------------------------------------------------------
// Dual SPMM.
// out_i[r] = alpha_i(inv) * S_i(r) + beta_i(inv) * X_i[r]
// with S_i(r) = sum over non-self edges of row r of X_i[col[e]],
// inv = 1/deg[r], deg[r] = (#edges of row r) + 1 (self loop).
// A^p: alpha = inv^p,            beta = inv^p
// L^p: alpha = (-inv)^p,         beta = (1-inv)^p
// X1A=true -> X1 gets A^P, X2 gets L^P (false: swapped).
// EPI: 0 store O1/O2, 1 acc = relu(o1)+relu(o2), 2 acc += relu(o1)+relu(o2)
// ---------------------------------------------------------------------------
template <int P>
__device__ __forceinline__ float powi(float v) {
    float r = v;
#pragma unroll
    for (int i = 1; i < P; i++) r *= v;
    return r;
}

template <int P, bool X1A, int EPI>
__global__ void spmm_dual_kernel(const float* __restrict__ X1f,
                                 const float* __restrict__ X2f,
                                 const int* __restrict__ col,
                                 const int* __restrict__ rp,
                                 float* __restrict__ O1f,
                                 float* __restrict__ O2f,
                                 float* __restrict__ accf, int n) {
    const float4* __restrict__ X1 = (const float4*)X1f;
    const float4* __restrict__ X2 = (const float4*)X2f;
    int warp = blockIdx.x * (blockDim.x >> 5) + (threadIdx.x >> 5);
    int lane = threadIdx.x & 31;
    if (warp >= n) return;
    const int r = warp;
    const int start = rp[r];
    const int end = rp[r + 1];
    const float inv = 1.0f / (float)(end - start + 1);

    float4 s1 = make_float4(0.f, 0.f, 0.f, 0.f);
    float4 s2 = make_float4(0.f, 0.f, 0.f, 0.f);

    for (int base = start; base < end; base += 32) {
        int idx = base + lane;
        int myc = (idx < end) ? col[idx] : 0;
        int m = end - base;
        if (m > 32) m = 32;
        for (int j = 0; j < m; j++) {
            int c = __shfl_sync(0xffffffffu, myc, j);
            float4 a = __ldg(&X1[c * 32 + lane]);
            float4 b = __ldg(&X2[c * 32 + lane]);
            s1.x += a.x; s1.y += a.y; s1.z += a.z; s1.w += a.w;
            s2.x += b.x; s2.y += b.y; s2.z += b.z; s2.w += b.w;
        }
    }

    float4 x1 = __ldg(&X1[r * 32 + lane]);
    float4 x2 = __ldg(&X2[r * 32 + lane]);

    const float ip = powi<P>(inv);
    const float aA = ip, bA = ip;
    const float aL = (P & 1) ? -ip : ip;
    const float bL = powi<P>(1.0f - inv);
    const float a1 = X1A ? aA : aL, b1 = X1A ? bA : bL;
    const float a2 = X1A ? aL : aA, b2 = X1A ? bL : bA;

    float4 o1, o2;
    o1.x = fmaf(a1, s1.x, b1 * x1.x);
    o1.y = fmaf(a1, s1.y, b1 * x1.y);
    o1.z = fmaf(a1, s1.z, b1 * x1.z);
    o1.w = fmaf(a1, s1.w, b1 * x1.w);
    o2.x = fmaf(a2, s2.x, b2 * x2.x);
    o2.y = fmaf(a2, s2.y, b2 * x2.y);
    o2.z = fmaf(a2, s2.z, b2 * x2.z);
    o2.w = fmaf(a2, s2.w, b2 * x2.w);

    if (EPI == 0) {
        ((float4*)O1f)[r * 32 + lane] = o1;
        ((float4*)O2f)[r * 32 + lane] = o2;
    } else {
        float4 v;
        v.x = fmaxf(o1.x, 0.f) + fmaxf(o2.x, 0.f);
        v.y = fmaxf(o1.y, 0.f) + fmaxf(o2.y, 0.f);
        v.z = fmaxf(o1.z, 0.f) + fmaxf(o2.z, 0.f);
        v.w = fmaxf(o1.w, 0.f) + fmaxf(o2.w, 0.f);
        if (EPI == 2) {
            float4 p = ((float4*)accf)[r * 32 + lane];
            v.x += p.x; v.y += p.y; v.z += p.z; v.w += p.w;
        }
        ((float4*)accf)[r * 32 + lane] = v;
    }
}

// ---------------------------------------------------------------------------
// Launch
// ---------------------------------------------------------------------------
extern "C" void kernel_launch(void* const* d_in, const int* in_sizes, int n_in,
                              void* d_out, int out_size) {
    const float* x = (const float*)d_in[0];      // [n, 256]
    const float* Wl1 = (const float*)d_in[1];    // [256, 128]
    const float* bl1 = (const float*)d_in[2];    // [128]
    const float* W1 = (const float*)d_in[3];     // [4, 128, 128]
    const float* W2 = (const float*)d_in[4];     // [4, 128, 128]
    const float* Wl2 = (const float*)d_in[5];    // [128, 64]
    const float* bl2 = (const float*)d_in[6];    // [64]
    const int* ei = (const int*)d_in[7];         // [2, E]
    const int E = in_sizes[7] / 2;
    const int n = in_sizes[0] / 256;
    float* out = (float*)d_out;

    static float *h = nullptr, *t1, *t2, *u1, *u2, *acc;
    static int* rp;
    if (!h) {
        cudaGetSymbolAddress((void**)&h, g_h);
        cudaGetSymbolAddress((void**)&t1, g_t1);
        cudaGetSymbolAddress((void**)&t2, g_t2);
        cudaGetSymbolAddress((void**)&u1, g_u1);
        cudaGetSymbolAddress((void**)&u2, g_u2);
        cudaGetSymbolAddress((void**)&acc, g_acc);
        cudaGetSymbolAddress((void**)&rp, g_rp);
    }

    const int* rowv = ei;
    const int* colv = ei + E;

    rowptr_kernel<<<(n + 1 + 255) / 256, 256>>>(rowv, E, n, rp);

    dim3 g1((n + 127) / 128, 1);
    // h = relu(x @ W_lin1 + b)
    sgemm_kernel<128, 128, 16, 8, 8, true, true>
        <<<g1, 256>>>(x, Wl1, bl1, h, n, 128, 256, 1.0f);

    const int sb = (n + 7) / 8;  // one warp per row, 8 warps per block

    // ---- layer 0: o1 = A t1, o2 = L t2 ; acc = relu+relu
    sgemm_kernel<128, 128, 16, 8, 8, false, false>
        <<<g1, 256>>>(h, W1 + 0 * 128 * 128, nullptr, t1, n, 128, 128, 1.0f);
    sgemm_kernel<128, 128, 16, 8, 8, false, false>
        <<<g1, 256>>>(h, W2 + 0 * 128 * 128, nullptr, t2, n, 128, 128, 1.0f);
    spmm_dual_kernel<1, true, 1>
        <<<sb, 256>>>(t1, t2, colv, rp, nullptr, nullptr, acc, n);

    // ---- layer 1: u1 = L^1 t1, u2 = A^1 t2 ; then A u1, L u2 ; acc +=
    sgemm_kernel<128, 128, 16, 8, 8, false, false>
        <<<g1, 256>>>(h, W1 + 1 * 128 * 128, nullptr, t1, n, 128, 128, 1.0f);
    sgemm_kernel<128, 128, 16, 8, 8, false, false>
        <<<g1, 256>>>(h, W2 + 1 * 128 * 128, nullptr, t2, n, 128, 128, 1.0f);
    spmm_dual_kernel<1, false, 0>
        <<<sb, 256>>>(t1, t2, colv, rp, u1, u2, nullptr, n);
    spmm_dual_kernel<1, true, 2>
        <<<sb, 256>>>(u1, u2, colv, rp, nullptr, nullptr, acc, n);

    // ---- layer 2: u = (L^2 t1, A^2 t2) ; then (A u1, L u2) ; acc +=
    sgemm_kernel<128, 128, 16, 8, 8, false, false>
        <<<g1, 256>>>(h, W1 + 2 * 128 * 128, nullptr, t1, n, 128, 128, 1.0f);
    sgemm_kernel<128, 128, 16, 8, 8, false, false>
        <<<g1, 256>>>(h, W2 + 2 * 128 * 128, nullptr, t2, n, 128, 128, 1.0f);
    spmm_dual_kernel<2, false, 0>
        <<<sb, 256>>>(t1, t2, colv, rp, u1, u2, nullptr, n);
    spmm_dual_kernel<1, true, 2>
        <<<sb, 256>>>(u1, u2, colv, rp, nullptr, nullptr, acc, n);

    // ---- layer 3: o1 = L^3 t1, o2 = A^3 t2 ; acc +=
    sgemm_kernel<128, 128, 16, 8, 8, false, false>
        <<<g1, 256>>>(h, W1 + 3 * 128 * 128, nullptr, t1, n, 128, 128, 1.0f);
    sgemm_kernel<128, 128, 16, 8, 8, false, false>
        <<<g1, 256>>>(h, W2 + 3 * 128 * 128, nullptr, t2, n, 128, 128, 1.0f);
    spmm_dual_kernel<3, false, 2>
        <<<sb, 256>>>(t1, t2, colv, rp, nullptr, nullptr, acc, n);

    // out = (acc/8) @ W_lin2 + b_lin2
    dim3 gf((n + 127) / 128, 1);
    sgemm_kernel<128, 64, 16, 8, 4, false, true>
        <<<gf, 256>>>(acc, Wl2, bl2, out, n, 64, 128, 0.125f);
}